// round 8
// baseline (speedup 1.0000x reference)
#include <cuda_runtime.h>
#include <math.h>

// Problem dims
#define BB 32
#define PP 100
#define NN 1000
#define DD 128

// -------- device scratch (static, allocation-free) --------
__device__ float g_WkT[DD * DD];
__device__ float g_WvT[DD * DD];
__device__ float g_WqfT[DD * DD];
__device__ float g_WqlT[DD * DD];
__device__ float g_ek [BB * NN * DD];   // exp(k)
__device__ float g_ekv[BB * NN * DD];   // exp(k)*v
__device__ float g_ebias[BB * PP * NN]; // exp(c1*(-cur_dist)+mask)
__device__ float g_num[BB * PP * DD];
__device__ float g_den[BB * PP * DD];
__device__ float g_aft[BB * PP * DD];

// -------- kernel 1: transpose the four weight matrices (W[d][k] -> WT[k][d]) --------
__global__ void transpose_w(const float* __restrict__ Wk, const float* __restrict__ Wv,
                            const float* __restrict__ Wqf, const float* __restrict__ Wql) {
    int i = blockIdx.x * 256 + threadIdx.x;     // 64*256 = 16384 = DD*DD
    int d = i >> 7, k = i & 127;
    int o = k * DD + d;
    g_WkT [o] = Wk [i];
    g_WvT [o] = Wv [i];
    g_WqfT[o] = Wqf[i];
    g_WqlT[o] = Wql[i];
}

// -------- kernel 2: ebias = exp(mask - c1*cur_dist), c1 = log_scale*AFT_alpha --------
__global__ void ebias_kernel(const float* __restrict__ cur_dist, const float* __restrict__ mask,
                             const float* __restrict__ log_scale, const float* __restrict__ aft_alpha) {
    int i = blockIdx.x * 256 + threadIdx.x;     // 12500*256 = 3,200,000 exactly
    float c1 = log_scale[0] * aft_alpha[0];
    g_ebias[i] = __expf(fmaf(-c1, cur_dist[i], mask[i]));
}

// -------- kernel 3: k/v projection -> g_ek, g_ekv --------
// GEMM [32000 x 128] x [128 x (32 d-cols, both Wk & Wv)]; tile rows=64, thread = 4r x 4c x 2mats
__global__ __launch_bounds__(128) void kv_proj(const float* __restrict__ enc) {
    int d0 = blockIdx.x * 32;          // 4 d-tiles
    int r0 = blockIdx.y * 64;          // 500 row-tiles
    int tid = threadIdx.x;
    int rg = tid >> 3, cg = tid & 7;   // 16 rowgroups x 8 colgroups
    __shared__ float xs[64][17];
    __shared__ float wks[16][32];
    __shared__ float wvs[16][32];
    float aK[4][4] = {}, aV[4][4] = {};
    for (int k0 = 0; k0 < 128; k0 += 16) {
        for (int i = tid; i < 1024; i += 128) {
            int r = i >> 4, kk = i & 15;
            xs[r][kk] = enc[(size_t)(r0 + r) * DD + k0 + kk];
        }
        for (int i = tid; i < 512; i += 128) {
            int kk = i >> 5, c = i & 31;
            wks[kk][c] = g_WkT[(k0 + kk) * DD + d0 + c];
            wvs[kk][c] = g_WvT[(k0 + kk) * DD + d0 + c];
        }
        __syncthreads();
#pragma unroll
        for (int kk = 0; kk < 16; kk++) {
            float x[4];
#pragma unroll
            for (int j = 0; j < 4; j++) x[j] = xs[rg * 4 + j][kk];
            float4 wk4 = *(const float4*)&wks[kk][cg * 4];
            float4 wv4 = *(const float4*)&wvs[kk][cg * 4];
#pragma unroll
            for (int j = 0; j < 4; j++) {
                aK[j][0] += x[j] * wk4.x; aK[j][1] += x[j] * wk4.y;
                aK[j][2] += x[j] * wk4.z; aK[j][3] += x[j] * wk4.w;
                aV[j][0] += x[j] * wv4.x; aV[j][1] += x[j] * wv4.y;
                aV[j][2] += x[j] * wv4.z; aV[j][3] += x[j] * wv4.w;
            }
        }
        __syncthreads();
    }
#pragma unroll
    for (int j = 0; j < 4; j++) {
        size_t row = r0 + rg * 4 + j;
#pragma unroll
        for (int i = 0; i < 4; i++) {
            size_t o = row * DD + d0 + cg * 4 + i;
            float e = __expf(aK[j][i]);
            g_ek [o] = e;
            g_ekv[o] = e * aV[j][i];
        }
    }
}

// -------- kernel 4: AFT num/den = ebias[100x1000] @ ekv/ek[1000x64-col-tile] --------
// grid (4 coltiles, 32 batches), 160 threads, thread = 5 rows x 8 cols
__global__ __launch_bounds__(160) void aft_gemm() {
    int ct = blockIdx.x;               // 0,1 -> num (ekv); 2,3 -> den (ek)
    int b  = blockIdx.y;
    const float* __restrict__ src = (ct < 2) ? g_ekv : g_ek;
    float* __restrict__ dst = (ct < 2) ? g_num : g_den;
    int dbase = (ct & 1) * 64;
    int tid = threadIdx.x;
    int pg = tid >> 3, cg = tid & 7;   // pg 0..19 (5 rows each), cg 0..7 (8 cols each)
    __shared__ float ebs[100][40];
    __shared__ float ms[40][64];
    float acc[5][8] = {};
    for (int n0 = 0; n0 < NN; n0 += 40) {
        for (int i = tid; i < 4000; i += 160) {
            int p = i / 40, nn = i - p * 40;
            ebs[p][nn] = g_ebias[((size_t)b * PP + p) * NN + n0 + nn];
        }
        for (int i = tid; i < 2560; i += 160) {
            int nn = i >> 6, c = i & 63;
            ms[nn][c] = src[((size_t)b * NN + n0 + nn) * DD + dbase + c];
        }
        __syncthreads();
#pragma unroll 4
        for (int nn = 0; nn < 40; nn++) {
            float eb[5];
#pragma unroll
            for (int j = 0; j < 5; j++) eb[j] = ebs[pg * 5 + j][nn];
            float4 m0 = *(const float4*)&ms[nn][cg * 8];
            float4 m1 = *(const float4*)&ms[nn][cg * 8 + 4];
#pragma unroll
            for (int j = 0; j < 5; j++) {
                acc[j][0] += eb[j] * m0.x; acc[j][1] += eb[j] * m0.y;
                acc[j][2] += eb[j] * m0.z; acc[j][3] += eb[j] * m0.w;
                acc[j][4] += eb[j] * m1.x; acc[j][5] += eb[j] * m1.y;
                acc[j][6] += eb[j] * m1.z; acc[j][7] += eb[j] * m1.w;
            }
        }
        __syncthreads();
    }
#pragma unroll
    for (int j = 0; j < 5; j++) {
        int p = pg * 5 + j;
        size_t base = ((size_t)b * PP + p) * DD + dbase + cg * 8;
        float4 s0 = make_float4(acc[j][0], acc[j][1], acc[j][2], acc[j][3]);
        float4 s1 = make_float4(acc[j][4], acc[j][5], acc[j][6], acc[j][7]);
        *(float4*)&dst[base]     = s0;
        *(float4*)&dst[base + 4] = s1;
    }
}

// -------- kernel 5: q = x1@WqfT + x2@WqlT; aft = sigmoid(q)*num/den --------
// rows 3200, tile rows=64 x 32 d-cols, 128 threads, thread = 4r x 4c (summed dual GEMM)
__global__ __launch_bounds__(128) void q_aft(const float* __restrict__ x1, const float* __restrict__ x2) {
    int d0 = blockIdx.x * 32;          // 4 d-tiles
    int r0 = blockIdx.y * 64;          // 50 row-tiles (rows = b*100+p)
    int tid = threadIdx.x;
    int rg = tid >> 3, cg = tid & 7;
    __shared__ float x1s[64][17];
    __shared__ float x2s[64][17];
    __shared__ float wfs[16][32];
    __shared__ float wls[16][32];
    float acc[4][4] = {};
    for (int k0 = 0; k0 < 128; k0 += 16) {
        for (int i = tid; i < 1024; i += 128) {
            int r = i >> 4, kk = i & 15;
            size_t g = (size_t)(r0 + r) * DD + k0 + kk;
            x1s[r][kk] = x1[g];
            x2s[r][kk] = x2[g];
        }
        for (int i = tid; i < 512; i += 128) {
            int kk = i >> 5, c = i & 31;
            wfs[kk][c] = g_WqfT[(k0 + kk) * DD + d0 + c];
            wls[kk][c] = g_WqlT[(k0 + kk) * DD + d0 + c];
        }
        __syncthreads();
#pragma unroll
        for (int kk = 0; kk < 16; kk++) {
            float a[4], b2[4];
#pragma unroll
            for (int j = 0; j < 4; j++) { a[j] = x1s[rg * 4 + j][kk]; b2[j] = x2s[rg * 4 + j][kk]; }
            float4 wf4 = *(const float4*)&wfs[kk][cg * 4];
            float4 wl4 = *(const float4*)&wls[kk][cg * 4];
#pragma unroll
            for (int j = 0; j < 4; j++) {
                acc[j][0] += a[j] * wf4.x + b2[j] * wl4.x;
                acc[j][1] += a[j] * wf4.y + b2[j] * wl4.y;
                acc[j][2] += a[j] * wf4.z + b2[j] * wl4.z;
                acc[j][3] += a[j] * wf4.w + b2[j] * wl4.w;
            }
        }
        __syncthreads();
    }
#pragma unroll
    for (int j = 0; j < 4; j++) {
        size_t row = r0 + rg * 4 + j;
#pragma unroll
        for (int i = 0; i < 4; i++) {
            size_t o = row * DD + d0 + cg * 4 + i;
            float q = acc[j][i];
            float sg = 1.0f / (1.0f + __expf(-q));
            g_aft[o] = sg * g_num[o] / g_den[o];
        }
    }
}

// -------- kernel 6: score = 10*tanh(aft@encT/sqrtD - c2*cur_dist) + mask --------
// grid (25 n-tiles of 40, 32 batches), 200 threads, thread = 5p x 4n
__global__ __launch_bounds__(200) void score_gemm(const float* __restrict__ enc,
                                                  const float* __restrict__ cur_dist,
                                                  const float* __restrict__ mask,
                                                  const float* __restrict__ log_scale,
                                                  const float* __restrict__ dist_alpha,
                                                  float* __restrict__ out) {
    int n0 = blockIdx.x * 40;
    int b  = blockIdx.y;
    int tid = threadIdx.x;
    int pg = tid / 10, cg = tid - pg * 10;   // pg 0..19 (5 rows), cg 0..9 (4 n-cols)
    __shared__ float afts[100][17];
    __shared__ float encs[16][44];
    float acc[5][4] = {};
    for (int k0 = 0; k0 < 128; k0 += 16) {
        for (int i = tid; i < 1600; i += 200) {
            int p = i >> 4, kk = i & 15;
            afts[p][kk] = g_aft[((size_t)b * PP + p) * DD + k0 + kk];
        }
        for (int i = tid; i < 640; i += 200) {
            int nn = i >> 4, kk = i & 15;
            encs[kk][nn] = enc[((size_t)b * NN + n0 + nn) * DD + k0 + kk];
        }
        __syncthreads();
#pragma unroll
        for (int kk = 0; kk < 16; kk++) {
            float a[5];
#pragma unroll
            for (int j = 0; j < 5; j++) a[j] = afts[pg * 5 + j][kk];
            float4 e4 = *(const float4*)&encs[kk][cg * 4];
#pragma unroll
            for (int j = 0; j < 5; j++) {
                acc[j][0] += a[j] * e4.x; acc[j][1] += a[j] * e4.y;
                acc[j][2] += a[j] * e4.z; acc[j][3] += a[j] * e4.w;
            }
        }
        __syncthreads();
    }
    float c2 = log_scale[0] * dist_alpha[0];
    const float inv_sqrt_d = 0.08838834764831845f;   // 1/sqrt(128)
#pragma unroll
    for (int j = 0; j < 5; j++) {
        int p = pg * 5 + j;
        size_t base = ((size_t)b * PP + p) * NN + n0 + cg * 4;
        float4 cd = *(const float4*)(cur_dist + base);
        float4 mk = *(const float4*)(mask + base);
        float4 r;
        r.x = 10.0f * tanhf(acc[j][0] * inv_sqrt_d - c2 * cd.x) + mk.x;
        r.y = 10.0f * tanhf(acc[j][1] * inv_sqrt_d - c2 * cd.y) + mk.y;
        r.z = 10.0f * tanhf(acc[j][2] * inv_sqrt_d - c2 * cd.z) + mk.z;
        r.w = 10.0f * tanhf(acc[j][3] * inv_sqrt_d - c2 * cd.w) + mk.w;
        *(float4*)(out + base) = r;
    }
}

// -------- kernel 7: row softmax over N=1000, in place on out --------
__global__ __launch_bounds__(256) void softmax_rows(float* __restrict__ out) {
    size_t row = blockIdx.x;
    float* p = out + row * NN;
    int tid = threadIdx.x;
    float v[4];
    int cnt = 0;
    float mx = -3.0e38f;
    for (int i = tid; i < NN; i += 256) { v[cnt] = p[i]; mx = fmaxf(mx, v[cnt]); cnt++; }
#pragma unroll
    for (int o = 16; o; o >>= 1) mx = fmaxf(mx, __shfl_xor_sync(0xffffffffu, mx, o));
    __shared__ float sm[8], ss[8];
    int w = tid >> 5, l = tid & 31;
    if (l == 0) sm[w] = mx;
    __syncthreads();
    float m = sm[0];
#pragma unroll
    for (int i = 1; i < 8; i++) m = fmaxf(m, sm[i]);
    float s = 0.0f;
    for (int c = 0; c < cnt; c++) { v[c] = __expf(v[c] - m); s += v[c]; }
#pragma unroll
    for (int o = 16; o; o >>= 1) s += __shfl_xor_sync(0xffffffffu, s, o);
    if (l == 0) ss[w] = s;
    __syncthreads();
    float tot = 0.0f;
#pragma unroll
    for (int i = 0; i < 8; i++) tot += ss[i];
    float inv = 1.0f / tot;
    cnt = 0;
    for (int i = tid; i < NN; i += 256) { p[i] = v[cnt] * inv; cnt++; }
}

extern "C" void kernel_launch(void* const* d_in, const int* in_sizes, int n_in,
                              void* d_out, int out_size) {
    const float* enc        = (const float*)d_in[0];   // [B,N,D]
    const float* q1         = (const float*)d_in[1];   // [B,P,D]
    const float* last       = (const float*)d_in[2];   // [B,P,D]
    const float* cur_dist   = (const float*)d_in[3];   // [B,P,N]
    const float* ninf_mask  = (const float*)d_in[4];   // [B,P,N]
    const float* log_scale  = (const float*)d_in[5];   // [1]
    const float* Wq_first   = (const float*)d_in[6];   // [D,D]
    const float* Wq_last    = (const float*)d_in[7];   // [D,D]
    const float* Wk         = (const float*)d_in[8];   // [D,D]
    const float* Wv         = (const float*)d_in[9];   // [D,D]
    const float* dist_alpha = (const float*)d_in[10];  // [1]
    const float* aft_alpha  = (const float*)d_in[11];  // [1]
    float* out = (float*)d_out;                        // [B,P,N]

    transpose_w<<<64, 256>>>(Wk, Wv, Wq_first, Wq_last);
    ebias_kernel<<<12500, 256>>>(cur_dist, ninf_mask, log_scale, aft_alpha);
    kv_proj<<<dim3(4, 500), 128>>>(enc);
    aft_gemm<<<dim3(4, 32), 160>>>();
    q_aft<<<dim3(4, 50), 128>>>(q1, last);
    score_gemm<<<dim3(25, 32), 200>>>(enc, cur_dist, ninf_mask, log_scale, dist_alpha, out);
    softmax_rows<<<3200, 256>>>(out);
}

// round 9
// speedup vs baseline: 1.2859x; 1.2859x over previous
#include <cuda_runtime.h>
#include <math.h>

// Problem dims
#define BB 32
#define PP 100
#define NN 1000
#define DD 128
#define SPLIT 4
#define ROWS (BB*PP)           // 3200
#define RD   ((size_t)ROWS*DD) // 409600

// -------- device scratch (static, allocation-free) --------
__device__ float g_WkT [DD*DD];
__device__ float g_WvT [DD*DD];
__device__ float g_WqfT[DD*DD];
__device__ float g_WqlT[DD*DD];
__device__ float g_ek  [(size_t)BB*NN*DD];  // exp(k)
__device__ float g_ekv [(size_t)BB*NN*DD];  // exp(k)*v
__device__ float g_pnum[SPLIT*RD];          // K-split partials
__device__ float g_pden[SPLIT*RD];
__device__ float g_aft [RD];

// -------- packed f32x2 helpers (sm_103a) --------
__device__ __forceinline__ void fma2(unsigned long long& d, unsigned long long a, unsigned long long b) {
    asm("fma.rn.f32x2 %0, %1, %2, %0;" : "+l"(d) : "l"(a), "l"(b));
}
__device__ __forceinline__ float2 unpk(unsigned long long v) {
    float2 r; asm("mov.b64 {%0, %1}, %2;" : "=f"(r.x), "=f"(r.y) : "l"(v)); return r;
}

// -------- kernel 1: transpose the four weight matrices --------
__global__ void transpose_w(const float* __restrict__ Wk, const float* __restrict__ Wv,
                            const float* __restrict__ Wqf, const float* __restrict__ Wql) {
    int i = blockIdx.x * 256 + threadIdx.x;     // 64*256 = 16384 = DD*DD
    int d = i >> 7, k = i & 127;
    int o = k * DD + d;
    g_WkT [o] = Wk [i];
    g_WvT [o] = Wv [i];
    g_WqfT[o] = Wqf[i];
    g_WqlT[o] = Wql[i];
}

// -------- kernel 2: k/v projection (f32x2) -> g_ek, g_ekv --------
// [32000 x 128] x [128 x 32cols] for both Wk and Wv; thread = 4r x 4c x 2mats
__global__ __launch_bounds__(128) void kv_proj(const float* __restrict__ enc) {
    int d0 = blockIdx.x * 32;          // 4 d-tiles
    int r0 = blockIdx.y * 64;          // 500 row-tiles
    int tid = threadIdx.x;
    int rg = tid >> 3, cg = tid & 7;   // 16 rowgroups x 8 colgroups
    __shared__ __align__(16) float2 xs2[64][16];   // x duplicated into both halves
    __shared__ __align__(16) float  wks[16][32];
    __shared__ __align__(16) float  wvs[16][32];
    unsigned long long aK[4][2] = {}, aV[4][2] = {};
    for (int k0 = 0; k0 < 128; k0 += 16) {
        for (int i = tid; i < 1024; i += 128) {
            int r = i >> 4, kk = i & 15;
            float v = enc[(size_t)(r0 + r) * DD + k0 + kk];
            xs2[r][kk] = make_float2(v, v);
        }
        for (int i = tid; i < 512; i += 128) {
            int kk = i >> 5, c = i & 31;
            wks[kk][c] = g_WkT[(k0 + kk) * DD + d0 + c];
            wvs[kk][c] = g_WvT[(k0 + kk) * DD + d0 + c];
        }
        __syncthreads();
#pragma unroll
        for (int kk = 0; kk < 16; kk++) {
            unsigned long long x[4];
#pragma unroll
            for (int j = 0; j < 4; j++) x[j] = *(const unsigned long long*)&xs2[rg * 4 + j][kk];
            ulonglong2 wk = *(const ulonglong2*)&wks[kk][cg * 4];
            ulonglong2 wv = *(const ulonglong2*)&wvs[kk][cg * 4];
#pragma unroll
            for (int j = 0; j < 4; j++) {
                fma2(aK[j][0], x[j], wk.x); fma2(aK[j][1], x[j], wk.y);
                fma2(aV[j][0], x[j], wv.x); fma2(aV[j][1], x[j], wv.y);
            }
        }
        __syncthreads();
    }
#pragma unroll
    for (int j = 0; j < 4; j++) {
        size_t o = (size_t)(r0 + rg * 4 + j) * DD + d0 + cg * 4;
        float2 k01 = unpk(aK[j][0]), k23 = unpk(aK[j][1]);
        float2 v01 = unpk(aV[j][0]), v23 = unpk(aV[j][1]);
        float e0 = __expf(k01.x), e1 = __expf(k01.y), e2 = __expf(k23.x), e3 = __expf(k23.y);
        *(float4*)&g_ek [o] = make_float4(e0, e1, e2, e3);
        *(float4*)&g_ekv[o] = make_float4(e0 * v01.x, e1 * v01.y, e2 * v23.x, e3 * v23.y);
    }
}

// -------- kernel 3: AFT partial num/den, fused, K-split, inline exp --------
// grid (SPLIT, 2 ptiles of 50, 32 b), 320 threads, thread = 5p x 4d x {num,den}
__global__ __launch_bounds__(320) void aft_partial(const float* __restrict__ cur_dist,
                                                   const float* __restrict__ mask,
                                                   const float* __restrict__ log_scale,
                                                   const float* __restrict__ aft_alpha) {
    int s  = blockIdx.x;               // K-split index (250 n each)
    int p0 = blockIdx.y * 50;          // p tile within batch
    int b  = blockIdx.z;
    int tid = threadIdx.x;
    int pg = tid >> 5, cg = tid & 31;  // warp = one pg (rows pg*5..+4), lanes cover d
    float c1 = log_scale[0] * aft_alpha[0];
    __shared__ __align__(16) float2 eb2[50][25];   // exp(bias), duplicated halves
    __shared__ __align__(16) float  msk[25][128];  // ek chunk
    __shared__ __align__(16) float  msv[25][128];  // ekv chunk
    unsigned long long aN[5][2] = {}, aD[5][2] = {};
    for (int c = 0; c < 10; c++) {
        int n0 = s * 250 + c * 25;
        for (int i = tid; i < 1250; i += 320) {
            int p = i / 25, nn = i - p * 25;
            size_t g = ((size_t)b * PP + p0 + p) * NN + n0 + nn;
            float e = __expf(fmaf(-c1, cur_dist[g], mask[g]));
            eb2[p][nn] = make_float2(e, e);
        }
        for (int i = tid; i < 1600; i += 320) {
            if (i < 800) {
                int nn = i >> 5, cc = i & 31;
                *(float4*)&msk[nn][cc * 4] =
                    *(const float4*)&g_ek[((size_t)b * NN + n0 + nn) * DD + cc * 4];
            } else {
                int ii = i - 800;
                int nn = ii >> 5, cc = ii & 31;
                *(float4*)&msv[nn][cc * 4] =
                    *(const float4*)&g_ekv[((size_t)b * NN + n0 + nn) * DD + cc * 4];
            }
        }
        __syncthreads();
#pragma unroll 5
        for (int nn = 0; nn < 25; nn++) {
            unsigned long long e[5];
#pragma unroll
            for (int j = 0; j < 5; j++) e[j] = *(const unsigned long long*)&eb2[pg * 5 + j][nn];
            ulonglong2 k2 = *(const ulonglong2*)&msk[nn][cg * 4];
            ulonglong2 v2 = *(const ulonglong2*)&msv[nn][cg * 4];
#pragma unroll
            for (int j = 0; j < 5; j++) {
                fma2(aN[j][0], e[j], v2.x); fma2(aN[j][1], e[j], v2.y);
                fma2(aD[j][0], e[j], k2.x); fma2(aD[j][1], e[j], k2.y);
            }
        }
        __syncthreads();
    }
#pragma unroll
    for (int j = 0; j < 5; j++) {
        int row = b * PP + p0 + pg * 5 + j;
        size_t o = (size_t)s * RD + (size_t)row * DD + cg * 4;
        float2 n01 = unpk(aN[j][0]), n23 = unpk(aN[j][1]);
        float2 d01 = unpk(aD[j][0]), d23 = unpk(aD[j][1]);
        *(float4*)&g_pnum[o] = make_float4(n01.x, n01.y, n23.x, n23.y);
        *(float4*)&g_pden[o] = make_float4(d01.x, d01.y, d23.x, d23.y);
    }
}

// -------- kernel 4: q = x1@WqfT + x2@WqlT; aft = sigmoid(q)*num/den --------
__global__ __launch_bounds__(128) void q_aft(const float* __restrict__ x1, const float* __restrict__ x2) {
    int d0 = blockIdx.x * 32;          // 4 d-tiles
    int r0 = blockIdx.y * 64;          // 50 row-tiles
    int tid = threadIdx.x;
    int rg = tid >> 3, cg = tid & 7;
    __shared__ float x1s[64][17];
    __shared__ float x2s[64][17];
    __shared__ float wfs[16][32];
    __shared__ float wls[16][32];
    float acc[4][4] = {};
    for (int k0 = 0; k0 < 128; k0 += 16) {
        for (int i = tid; i < 1024; i += 128) {
            int r = i >> 4, kk = i & 15;
            size_t g = (size_t)(r0 + r) * DD + k0 + kk;
            x1s[r][kk] = x1[g];
            x2s[r][kk] = x2[g];
        }
        for (int i = tid; i < 512; i += 128) {
            int kk = i >> 5, c = i & 31;
            wfs[kk][c] = g_WqfT[(k0 + kk) * DD + d0 + c];
            wls[kk][c] = g_WqlT[(k0 + kk) * DD + d0 + c];
        }
        __syncthreads();
#pragma unroll
        for (int kk = 0; kk < 16; kk++) {
            float a[4], b2[4];
#pragma unroll
            for (int j = 0; j < 4; j++) { a[j] = x1s[rg * 4 + j][kk]; b2[j] = x2s[rg * 4 + j][kk]; }
            float4 wf4 = *(const float4*)&wfs[kk][cg * 4];
            float4 wl4 = *(const float4*)&wls[kk][cg * 4];
#pragma unroll
            for (int j = 0; j < 4; j++) {
                acc[j][0] += a[j] * wf4.x + b2[j] * wl4.x;
                acc[j][1] += a[j] * wf4.y + b2[j] * wl4.y;
                acc[j][2] += a[j] * wf4.z + b2[j] * wl4.z;
                acc[j][3] += a[j] * wf4.w + b2[j] * wl4.w;
            }
        }
        __syncthreads();
    }
#pragma unroll
    for (int j = 0; j < 4; j++) {
        size_t o = (size_t)(r0 + rg * 4 + j) * DD + d0 + cg * 4;
        float4 ns = make_float4(0.f, 0.f, 0.f, 0.f), ds = make_float4(0.f, 0.f, 0.f, 0.f);
#pragma unroll
        for (int s = 0; s < SPLIT; s++) {
            float4 n4 = *(const float4*)&g_pnum[(size_t)s * RD + o];
            float4 d4 = *(const float4*)&g_pden[(size_t)s * RD + o];
            ns.x += n4.x; ns.y += n4.y; ns.z += n4.z; ns.w += n4.w;
            ds.x += d4.x; ds.y += d4.y; ds.z += d4.z; ds.w += d4.w;
        }
        float4 r;
        r.x = ns.x / ds.x / (1.0f + __expf(-acc[j][0]));
        r.y = ns.y / ds.y / (1.0f + __expf(-acc[j][1]));
        r.z = ns.z / ds.z / (1.0f + __expf(-acc[j][2]));
        r.w = ns.w / ds.w / (1.0f + __expf(-acc[j][3]));
        *(float4*)&g_aft[o] = r;
    }
}

// -------- kernel 5: score = 10*tanh(aft@encT/sqrtD - c2*cur_dist) + mask (f32x2) --------
__global__ __launch_bounds__(200) void score_gemm(const float* __restrict__ enc,
                                                  const float* __restrict__ cur_dist,
                                                  const float* __restrict__ mask,
                                                  const float* __restrict__ log_scale,
                                                  const float* __restrict__ dist_alpha,
                                                  float* __restrict__ out) {
    int n0 = blockIdx.x * 40;
    int b  = blockIdx.y;
    int tid = threadIdx.x;
    int pg = tid / 10, cg = tid - pg * 10;    // 20 pg x 10 cg; thread = 5p x 4n
    __shared__ __align__(16) float2 afts2[100][16];
    __shared__ __align__(16) float  encs[16][44];
    unsigned long long acc[5][2] = {};
    for (int k0 = 0; k0 < 128; k0 += 16) {
        for (int i = tid; i < 1600; i += 200) {
            int p = i >> 4, kk = i & 15;
            float v = g_aft[((size_t)b * PP + p) * DD + k0 + kk];
            afts2[p][kk] = make_float2(v, v);
        }
        for (int i = tid; i < 640; i += 200) {
            int nn = i >> 4, kk = i & 15;
            encs[kk][nn] = enc[((size_t)b * NN + n0 + nn) * DD + k0 + kk];
        }
        __syncthreads();
#pragma unroll
        for (int kk = 0; kk < 16; kk++) {
            unsigned long long a[5];
#pragma unroll
            for (int j = 0; j < 5; j++) a[j] = *(const unsigned long long*)&afts2[pg * 5 + j][kk];
            ulonglong2 e2 = *(const ulonglong2*)&encs[kk][cg * 4];
#pragma unroll
            for (int j = 0; j < 5; j++) {
                fma2(acc[j][0], a[j], e2.x);
                fma2(acc[j][1], a[j], e2.y);
            }
        }
        __syncthreads();
    }
    float c2 = log_scale[0] * dist_alpha[0];
    const float inv_sqrt_d = 0.08838834764831845f;   // 1/sqrt(128)
#pragma unroll
    for (int j = 0; j < 5; j++) {
        int p = pg * 5 + j;
        size_t base = ((size_t)b * PP + p) * NN + n0 + cg * 4;
        float4 cd = *(const float4*)(cur_dist + base);
        float4 mk = *(const float4*)(mask + base);
        float2 a01 = unpk(acc[j][0]), a23 = unpk(acc[j][1]);
        float4 r;
        r.x = 10.0f * tanhf(a01.x * inv_sqrt_d - c2 * cd.x) + mk.x;
        r.y = 10.0f * tanhf(a01.y * inv_sqrt_d - c2 * cd.y) + mk.y;
        r.z = 10.0f * tanhf(a23.x * inv_sqrt_d - c2 * cd.z) + mk.z;
        r.w = 10.0f * tanhf(a23.y * inv_sqrt_d - c2 * cd.w) + mk.w;
        *(float4*)(out + base) = r;
    }
}

// -------- kernel 6: row softmax over N=1000, in place --------
__global__ __launch_bounds__(256) void softmax_rows(float* __restrict__ out) {
    size_t row = blockIdx.x;
    float* p = out + row * NN;
    int tid = threadIdx.x;
    float v[4];
    int cnt = 0;
    float mx = -3.0e38f;
    for (int i = tid; i < NN; i += 256) { v[cnt] = p[i]; mx = fmaxf(mx, v[cnt]); cnt++; }
#pragma unroll
    for (int o = 16; o; o >>= 1) mx = fmaxf(mx, __shfl_xor_sync(0xffffffffu, mx, o));
    __shared__ float sm[8], ss[8];
    int w = tid >> 5, l = tid & 31;
    if (l == 0) sm[w] = mx;
    __syncthreads();
    float m = sm[0];
#pragma unroll
    for (int i = 1; i < 8; i++) m = fmaxf(m, sm[i]);
    float s = 0.0f;
    for (int c = 0; c < cnt; c++) { v[c] = __expf(v[c] - m); s += v[c]; }
#pragma unroll
    for (int o = 16; o; o >>= 1) s += __shfl_xor_sync(0xffffffffu, s, o);
    if (l == 0) ss[w] = s;
    __syncthreads();
    float tot = 0.0f;
#pragma unroll
    for (int i = 0; i < 8; i++) tot += ss[i];
    float inv = 1.0f / tot;
    cnt = 0;
    for (int i = tid; i < NN; i += 256) { p[i] = v[cnt] * inv; cnt++; }
}

extern "C" void kernel_launch(void* const* d_in, const int* in_sizes, int n_in,
                              void* d_out, int out_size) {
    const float* enc        = (const float*)d_in[0];   // [B,N,D]
    const float* q1         = (const float*)d_in[1];   // [B,P,D]
    const float* last       = (const float*)d_in[2];   // [B,P,D]
    const float* cur_dist   = (const float*)d_in[3];   // [B,P,N]
    const float* ninf_mask  = (const float*)d_in[4];   // [B,P,N]
    const float* log_scale  = (const float*)d_in[5];   // [1]
    const float* Wq_first   = (const float*)d_in[6];   // [D,D]
    const float* Wq_last    = (const float*)d_in[7];   // [D,D]
    const float* Wk         = (const float*)d_in[8];   // [D,D]
    const float* Wv         = (const float*)d_in[9];   // [D,D]
    const float* dist_alpha = (const float*)d_in[10];  // [1]
    const float* aft_alpha  = (const float*)d_in[11];  // [1]
    float* out = (float*)d_out;                        // [B,P,N]

    transpose_w<<<64, 256>>>(Wk, Wv, Wq_first, Wq_last);
    kv_proj<<<dim3(4, 500), 128>>>(enc);
    aft_partial<<<dim3(SPLIT, 2, BB), 320>>>(cur_dist, ninf_mask, log_scale, aft_alpha);
    q_aft<<<dim3(4, 50), 128>>>(q1, last);
    score_gemm<<<dim3(25, 32), 200>>>(enc, cur_dist, ninf_mask, log_scale, dist_alpha, out);
    softmax_rows<<<3200, 256>>>(out);
}